// round 10
// baseline (speedup 1.0000x reference)
#include <cuda_runtime.h>
#include <cstdint>
#include <cstddef>

// ---------------------------------------------------------------------------
// Problem dims
// ---------------------------------------------------------------------------
#define NROWS 16384
#define INF   512
#define OUTF  256

// GEMM tiling: CTA tile 128(M) x 128(N), 2 CTAs per SM, 3-stage pipeline
#define TILE_M 128
#define TILE_N 128
#define KC     32            // K elems per pipeline stage
#define PA     36            // A smem pitch (floats): LDS.32 bank = (4g+t)&31 distinct
#define PB     32            // B smem pitch (floats): exact, XOR-swizzled chunks
#define A_SM_FLOATS (TILE_M * PA)                    // 4608
#define B_SM_FLOATS (TILE_N * PB)                    // 4096
#define STAGE_FLOATS (A_SM_FLOATS + B_SM_FLOATS)     // 8704
#define NSTAGE 3
#define SMEM_BYTES (NSTAGE * STAGE_FLOATS * 4)       // 104448 -> 2 CTAs/SM (209KB)

// 32-block k permutation for B-side tensors (gT, wrn):
//   logical k = 16h + 4i + t  ->  physical = 16h + 4t + i
// so thread t's fragment pairs (t,t+4) of kstep 2h and (8+t,12+t) of kstep 2h+1
// occupy ONE contiguous 16-byte chunk (chunk index 4h+t) -> LDS.128.
__host__ __device__ __forceinline__ int perm32(int k) {
    int h = (k >> 4) & 1, r = k & 15, i = r >> 2, t = r & 3;
    return 16 * h + 4 * t + i;
}

// ---------------------------------------------------------------------------
// Scratch (__device__ globals: allocation-free)
// ---------------------------------------------------------------------------
__device__ __align__(256) float g_dhf[(size_t)NROWS * INF];   // hat_d*feature, tf32-rounded
__device__ __align__(256) float g_wrn[(size_t)OUTF * INF];    // W, tf32-rounded, perm32 k-layout
__device__ __align__(256) float g_gT [(size_t)OUTF * NROWS];  // g^T, tf32-rounded, perm32 k-layout

// ---------------------------------------------------------------------------
// Helpers
// ---------------------------------------------------------------------------
__device__ __forceinline__ uint32_t smem_u32(const void* p) {
    uint32_t a;
    asm("{ .reg .u64 t; cvta.to.shared.u64 t, %1; cvt.u32.u64 %0, t; }" : "=r"(a) : "l"(p));
    return a;
}

__device__ __forceinline__ float rna_tf32(float x) {
    uint32_t u;
    asm("cvt.rna.tf32.f32 %0, %1;" : "=r"(u) : "f"(x));
    return __uint_as_float(u);
}

__device__ __forceinline__ void cp16(uint32_t dst_smem, const float* src) {
    asm volatile("cp.async.cg.shared.global [%0], [%1], 16;"
                 :: "r"(dst_smem), "l"(src) : "memory");
}

__device__ __forceinline__ void mma_tf32(float* d, const uint32_t* a, uint32_t b0, uint32_t b1) {
    asm volatile(
        "mma.sync.aligned.m16n8k8.row.col.f32.tf32.tf32.f32 "
        "{%0,%1,%2,%3}, {%4,%5,%6,%7}, {%8,%9}, {%0,%1,%2,%3};"
        : "+f"(d[0]), "+f"(d[1]), "+f"(d[2]), "+f"(d[3])
        : "r"(a[0]), "r"(a[1]), "r"(a[2]), "r"(a[3]),
          "r"(b0), "r"(b1));
}

// ---------------------------------------------------------------------------
// Prep: dhf = rna(hat_d * feature);  wrn[r][perm32(k)] = rna(W[r][k])
// ---------------------------------------------------------------------------
__global__ void prep_kernel(const float* __restrict__ hat_d,
                            const float* __restrict__ feature,
                            const float* __restrict__ W) {
    size_t i = (size_t)blockIdx.x * blockDim.x + threadIdx.x;
    size_t stride = (size_t)gridDim.x * blockDim.x;

    const float4* f4 = reinterpret_cast<const float4*>(feature);
    float4* d4 = reinterpret_cast<float4*>(g_dhf);
    size_t total4 = (size_t)NROWS * INF / 4;
    for (size_t idx = i; idx < total4; idx += stride) {
        float4 f = f4[idx];
        float d = __ldg(hat_d + (idx >> 7));
        float4 o;
        o.x = rna_tf32(d * f.x);
        o.y = rna_tf32(d * f.y);
        o.z = rna_tf32(d * f.z);
        o.w = rna_tf32(d * f.w);
        d4[idx] = o;
    }

    size_t wtotal = (size_t)OUTF * INF;
    for (size_t idx = i; idx < wtotal; idx += stride) {
        int k = (int)(idx & (INF - 1));
        size_t row = idx >> 9;
        int kp = (k & ~31) | perm32(k & 31);
        g_wrn[row * INF + kp] = rna_tf32(W[idx]);
    }
}

// ---------------------------------------------------------------------------
// tf32 mma.sync GEMM: D[128 x 128] = Atile[128 x K] @ Btile[128 x K]^T
//   B (global) carries perm32 k-layout; A natural layout.
//   mode 0: g_gT[n][perm32-scattered m] = rna(D[m][n])            (GEMM1)
//   mode 1: out[m][n] = hat_d[m]*(D[m][n] + gT_perm[n][m]) + b[n] (GEMM2)
// 256 threads = 8 warps in 4(M) x 2(N); warp tile 32 x 64; 2 CTAs/SM.
// ---------------------------------------------------------------------------
__global__ void __launch_bounds__(256, 2)
gemm_tf32_kernel(const float* __restrict__ Ap, int a_ld,
                 const float* __restrict__ Bp, int b_ld,
                 int nstages, int mode,
                 const float* __restrict__ hat_d,
                 const float* __restrict__ bias,
                 float* __restrict__ out)
{
    extern __shared__ float sm[];
    const int tid = threadIdx.x;
    const int mtile = blockIdx.x;
    const int ntile = blockIdx.y;
    const int wid = tid >> 5;
    const int lane = tid & 31;
    const int wm = wid & 3;           // 0..3: M position (32 rows each)
    const int wn = wid >> 2;          // 0..1: N position (64 cols each)
    const int g = lane >> 2;          // groupID 0..7
    const int t = lane & 3;           // threadID in group 0..3

    float acc[2][8][4];
    #pragma unroll
    for (int mi = 0; mi < 2; ++mi)
        #pragma unroll
        for (int ni = 0; ni < 8; ++ni)
            #pragma unroll
            for (int r = 0; r < 4; ++r)
                acc[mi][ni][r] = 0.0f;

    const float* Agm = Ap + (size_t)mtile * TILE_M * a_ld;
    const float* Bgm = Bp + (size_t)ntile * TILE_N * b_ld;

    // ---- stage loader ----
    // A: 128 rows x 8 chunks (16B), natural. B: 128 rows x 8 chunks, with
    // per-row chunk XOR swizzle in smem: phys_chunk = j ^ ((row&1)<<2).
    auto load_stage = [&](int s) {
        const int buf = s % NSTAGE;
        float* As = sm + buf * STAGE_FLOATS;
        float* Bs = As + A_SM_FLOATS;
        const int k0 = s * KC;
        #pragma unroll
        for (int i = 0; i < 4; ++i) {
            int v = tid + i * 256;
            int row = v >> 3, j = v & 7;
            cp16(smem_u32(As + row * PA + j * 4),
                 Agm + (size_t)row * a_ld + k0 + j * 4);
        }
        #pragma unroll
        for (int i = 0; i < 4; ++i) {
            int v = tid + i * 256;
            int row = v >> 3, j = v & 7;
            int jc = j ^ ((row & 1) << 2);
            cp16(smem_u32(Bs + row * PB + jc * 4),
                 Bgm + (size_t)row * b_ld + k0 + j * 4);
        }
    };

    // prologue: 2 stages in flight
    load_stage(0);
    asm volatile("cp.async.commit_group;" ::: "memory");
    load_stage(1);
    asm volatile("cp.async.commit_group;" ::: "memory");

    const int bxor = (g & 1) << 2;

    for (int s = 0; s < nstages; ++s) {
        asm volatile("cp.async.wait_group 1;" ::: "memory");   // stage s resident
        __syncthreads();                                       // all warps past compute(s-1)

        if (s + 2 < nstages) load_stage(s + 2);
        asm volatile("cp.async.commit_group;" ::: "memory");   // uniform group count

        const int buf = s % NSTAGE;
        const float* As = sm + buf * STAGE_FLOATS;
        const float* Bs = As + A_SM_FLOATS;
        const float* Abase = As + (wm * 32 + g) * PA + t;
        const float* Bbase = Bs + (wn * 64 + g) * PB;

        float4 bf[8];     // B fragments for 2 consecutive ksteps
        #pragma unroll
        for (int kk = 0; kk < 4; ++kk) {
            const int h = kk >> 1;
            if ((kk & 1) == 0) {
                // one LDS.128 per ni covers ksteps 2h and 2h+1
                #pragma unroll
                for (int ni = 0; ni < 8; ++ni)
                    bf[ni] = *reinterpret_cast<const float4*>(
                        Bbase + ni * 8 * PB + 4 * ((4 * h + t) ^ bxor));
            }
            uint32_t a[2][4];
            const int ko = kk * 8;
            #pragma unroll
            for (int mi = 0; mi < 2; ++mi) {
                const float* p = Abase + mi * 16 * PA + ko;
                a[mi][0] = __float_as_uint(p[0]);
                a[mi][1] = __float_as_uint(p[8 * PA]);
                a[mi][2] = __float_as_uint(p[4]);
                a[mi][3] = __float_as_uint(p[8 * PA + 4]);
            }
            if ((kk & 1) == 0) {
                #pragma unroll
                for (int mi = 0; mi < 2; ++mi)
                    #pragma unroll
                    for (int ni = 0; ni < 8; ++ni)
                        mma_tf32(acc[mi][ni], a[mi],
                                 __float_as_uint(bf[ni].x), __float_as_uint(bf[ni].y));
            } else {
                #pragma unroll
                for (int mi = 0; mi < 2; ++mi)
                    #pragma unroll
                    for (int ni = 0; ni < 8; ++ni)
                        mma_tf32(acc[mi][ni], a[mi],
                                 __float_as_uint(bf[ni].z), __float_as_uint(bf[ni].w));
            }
        }
    }

    // ---- epilogue ----
    // Row positions within the 32-aligned block [mbase+32*?]:
    //   r0 logical = 16*mi + g      -> perm32 = 16*mi + 4*(g&3) + (g>>2)
    //   r1 logical = 16*mi + g + 8  -> perm32 = r0p + 2
    const int mbase = mtile * TILE_M + wm * 32;
    const int nbase = ntile * TILE_N + wn * 64;
    const int pg = 4 * (g & 3) + (g >> 2);

    if (mode == 0) {
        #pragma unroll
        for (int mi = 0; mi < 2; ++mi) {
            int r0p = mbase + mi * 16 + pg;
            int r1p = r0p + 2;
            #pragma unroll
            for (int ni = 0; ni < 8; ++ni) {
                int c0 = nbase + ni * 8 + 2 * t;
                int c1 = c0 + 1;
                g_gT[(size_t)c0 * NROWS + r0p] = rna_tf32(acc[mi][ni][0]);
                g_gT[(size_t)c1 * NROWS + r0p] = rna_tf32(acc[mi][ni][1]);
                g_gT[(size_t)c0 * NROWS + r1p] = rna_tf32(acc[mi][ni][2]);
                g_gT[(size_t)c1 * NROWS + r1p] = rna_tf32(acc[mi][ni][3]);
            }
        }
    } else {
        #pragma unroll
        for (int mi = 0; mi < 2; ++mi) {
            int r0 = mbase + mi * 16 + g;     // logical output row
            int r1 = r0 + 8;
            int r0p = mbase + mi * 16 + pg;   // permuted gT column
            int r1p = r0p + 2;
            float h0 = __ldg(hat_d + r0);
            float h1 = __ldg(hat_d + r1);
            #pragma unroll
            for (int ni = 0; ni < 8; ++ni) {
                int c0 = nbase + ni * 8 + 2 * t;
                int c1 = c0 + 1;
                float b0v = __ldg(bias + c0);
                float b1v = __ldg(bias + c1);
                float g00 = g_gT[(size_t)c0 * NROWS + r0p];
                float g01 = g_gT[(size_t)c1 * NROWS + r0p];
                float g10 = g_gT[(size_t)c0 * NROWS + r1p];
                float g11 = g_gT[(size_t)c1 * NROWS + r1p];
                float2 v0, v1;
                v0.x = fmaf(h0, acc[mi][ni][0] + g00, b0v);
                v0.y = fmaf(h0, acc[mi][ni][1] + g01, b1v);
                v1.x = fmaf(h1, acc[mi][ni][2] + g10, b0v);
                v1.y = fmaf(h1, acc[mi][ni][3] + g11, b1v);
                *reinterpret_cast<float2*>(out + (size_t)r0 * OUTF + c0) = v0;
                *reinterpret_cast<float2*>(out + (size_t)r1 * OUTF + c0) = v1;
            }
        }
    }
}

// ---------------------------------------------------------------------------
// Host side
// ---------------------------------------------------------------------------
extern "C" void kernel_launch(void* const* d_in, const int* in_sizes, int n_in,
                              void* d_out, int out_size) {
    const float *A = nullptr, *hat_d = nullptr, *feature = nullptr,
                *W = nullptr, *b = nullptr;
    for (int i = 0; i < n_in; ++i) {
        switch (in_sizes[i]) {
            case NROWS:       hat_d   = (const float*)d_in[i]; break;   // 16384
            case OUTF:        b       = (const float*)d_in[i]; break;   // 256
            case OUTF * INF:  W       = (const float*)d_in[i]; break;   // 131072
            case NROWS * INF: feature = (const float*)d_in[i]; break;   // 8388608
            default:          A       = (const float*)d_in[i]; break;   // 16384*16384
        }
    }

    void *p_dhf = nullptr, *p_wrn = nullptr, *p_gT = nullptr;
    cudaGetSymbolAddress(&p_dhf, g_dhf);
    cudaGetSymbolAddress(&p_wrn, g_wrn);
    cudaGetSymbolAddress(&p_gT,  g_gT);

    static bool attr_set = false;
    if (!attr_set) {
        cudaFuncSetAttribute(gemm_tf32_kernel,
                             cudaFuncAttributeMaxDynamicSharedMemorySize, SMEM_BYTES);
        attr_set = true;
    }

    prep_kernel<<<1024, 256>>>(hat_d, feature, W);

    // GEMM1: g^T = (dhf @ W^T)^T   K = 512 -> 16 stages  (B = wrn, perm32)
    gemm_tf32_kernel<<<dim3(NROWS / TILE_M, OUTF / TILE_N), 256, SMEM_BYTES>>>(
        (const float*)p_dhf, INF,
        (const float*)p_wrn, INF,
        INF / KC, 0, nullptr, nullptr, nullptr);

    // GEMM2: out = hat_d*(A@g + g) + b   K = 16384 -> 512 stages  (B = gT, perm32)
    gemm_tf32_kernel<<<dim3(NROWS / TILE_M, OUTF / TILE_N), 256, SMEM_BYTES>>>(
        A, NROWS,
        (const float*)p_gT, NROWS,
        NROWS / KC, 1, hat_d, b, (float*)d_out);

    (void)out_size;
}

// round 11
// speedup vs baseline: 1.0969x; 1.0969x over previous
#include <cuda_runtime.h>
#include <cstdint>
#include <cstddef>

// ---------------------------------------------------------------------------
// Problem dims
// ---------------------------------------------------------------------------
#define NROWS 16384
#define INF   512
#define OUTF  256

// GEMM tiling: CTA tile 128(M) x 256(N), warp tile 64x64, 1 CTA/SM, 3 stages
#define TILE_M 128
#define TILE_N 256
#define KC     32            // K elems per pipeline stage
#define PA     36            // A smem pitch (floats): LDS.32 bank = (4g+t)&31 distinct
#define PB     40            // B smem pitch (floats): LDS.64 conflict-free per half-warp
#define A_SM_FLOATS (TILE_M * PA)                    // 4608
#define B_SM_FLOATS (TILE_N * PB)                    // 10240
#define STAGE_FLOATS (A_SM_FLOATS + B_SM_FLOATS)     // 14848
#define NSTAGE 3
#define SMEM_BYTES (NSTAGE * STAGE_FLOATS * 4)       // 178176 (174 KB)

// within-8-block k permutation: logical k -> physical offset
// off(k) = 2*(k&3) + ((k>>2)&1)   (logical pair (t, t+4) -> adjacent (2t, 2t+1))
__host__ __device__ __forceinline__ int kperm8(int k) {
    return 2 * (k & 3) + ((k >> 2) & 1);
}

// ---------------------------------------------------------------------------
// Scratch (__device__ globals: allocation-free)
// ---------------------------------------------------------------------------
__device__ __align__(256) float g_dhf[(size_t)NROWS * INF];   // hat_d*feature, tf32-rounded
__device__ __align__(256) float g_wrn[(size_t)OUTF * INF];    // W, tf32-rounded, kperm8 layout
__device__ __align__(256) float g_gT [(size_t)OUTF * NROWS];  // g^T, tf32-rounded, kperm8 layout

// ---------------------------------------------------------------------------
// Helpers
// ---------------------------------------------------------------------------
__device__ __forceinline__ uint32_t smem_u32(const void* p) {
    uint32_t a;
    asm("{ .reg .u64 t; cvta.to.shared.u64 t, %1; cvt.u32.u64 %0, t; }" : "=r"(a) : "l"(p));
    return a;
}

__device__ __forceinline__ float rna_tf32(float x) {
    uint32_t u;
    asm("cvt.rna.tf32.f32 %0, %1;" : "=r"(u) : "f"(x));
    return __uint_as_float(u);
}

__device__ __forceinline__ void cp16(uint32_t dst_smem, const float* src) {
    asm volatile("cp.async.cg.shared.global [%0], [%1], 16;"
                 :: "r"(dst_smem), "l"(src) : "memory");
}

__device__ __forceinline__ void mma_tf32(float* d, const uint32_t* a, uint32_t b0, uint32_t b1) {
    asm volatile(
        "mma.sync.aligned.m16n8k8.row.col.f32.tf32.tf32.f32 "
        "{%0,%1,%2,%3}, {%4,%5,%6,%7}, {%8,%9}, {%0,%1,%2,%3};"
        : "+f"(d[0]), "+f"(d[1]), "+f"(d[2]), "+f"(d[3])
        : "r"(a[0]), "r"(a[1]), "r"(a[2]), "r"(a[3]),
          "r"(b0), "r"(b1));
}

// ---------------------------------------------------------------------------
// Prep: dhf = rna(hat_d * feature);  wrn[r][kperm8(k)] = rna(W[r][k])
// ---------------------------------------------------------------------------
__global__ void prep_kernel(const float* __restrict__ hat_d,
                            const float* __restrict__ feature,
                            const float* __restrict__ W) {
    size_t i = (size_t)blockIdx.x * blockDim.x + threadIdx.x;
    size_t stride = (size_t)gridDim.x * blockDim.x;

    const float4* f4 = reinterpret_cast<const float4*>(feature);
    float4* d4 = reinterpret_cast<float4*>(g_dhf);
    size_t total4 = (size_t)NROWS * INF / 4;
    for (size_t idx = i; idx < total4; idx += stride) {
        float4 f = f4[idx];
        float d = __ldg(hat_d + (idx >> 7));
        float4 o;
        o.x = rna_tf32(d * f.x);
        o.y = rna_tf32(d * f.y);
        o.z = rna_tf32(d * f.z);
        o.w = rna_tf32(d * f.w);
        d4[idx] = o;
    }

    size_t wtotal = (size_t)OUTF * INF;
    for (size_t idx = i; idx < wtotal; idx += stride) {
        int k = (int)(idx & (INF - 1));
        size_t row = idx >> 9;
        int kp = (k & ~7) | kperm8(k & 7);
        g_wrn[row * INF + kp] = rna_tf32(W[idx]);
    }
}

// ---------------------------------------------------------------------------
// tf32 mma.sync GEMM: D[128 x 256] = Atile[128 x K] @ Btile[256 x K]^T
//   B (global) carries kperm8 k-layout; A natural layout.
//   mode 0: g_gT[n][kperm8-scattered m] = rna(D[m][n])            (GEMM1)
//   mode 1: out[m][n] = hat_d[m]*(D[m][n] + gT_perm[n][m]) + b[n] (GEMM2)
// 256 threads = 8 warps in 2(M) x 4(N); warp tile 64 x 64; 1 CTA/SM.
// ---------------------------------------------------------------------------
__global__ void __launch_bounds__(256, 1)
gemm_tf32_kernel(const float* __restrict__ Ap, int a_ld,
                 const float* __restrict__ Bp, int b_ld,
                 int nstages, int mode,
                 const float* __restrict__ hat_d,
                 const float* __restrict__ bias,
                 float* __restrict__ out)
{
    extern __shared__ float sm[];
    const int tid = threadIdx.x;
    const int mtile = blockIdx.x;
    const int ntile = blockIdx.y;
    const int wid = tid >> 5;
    const int lane = tid & 31;
    const int wm = wid & 1;           // 0..1: M position (64 rows each)
    const int wn = wid >> 1;          // 0..3: N position (64 cols each)
    const int g = lane >> 2;          // groupID 0..7
    const int t = lane & 3;           // threadID in group 0..3

    float acc[4][8][4];
    #pragma unroll
    for (int mi = 0; mi < 4; ++mi)
        #pragma unroll
        for (int ni = 0; ni < 8; ++ni)
            #pragma unroll
            for (int r = 0; r < 4; ++r)
                acc[mi][ni][r] = 0.0f;

    const float* Agm = Ap + (size_t)mtile * TILE_M * a_ld;
    const float* Bgm = Bp + (size_t)ntile * TILE_N * b_ld;

    // ---- stage loader: A 1024 + B 2048 cp.async.16 across 256 threads ----
    auto load_stage = [&](int s) {
        const int buf = s % NSTAGE;
        float* As = sm + buf * STAGE_FLOATS;
        float* Bs = As + A_SM_FLOATS;
        const int k0 = s * KC;
        #pragma unroll
        for (int i = 0; i < 4; ++i) {
            int v = tid + i * 256;
            int row = v >> 3, j = v & 7;
            cp16(smem_u32(As + row * PA + j * 4),
                 Agm + (size_t)row * a_ld + k0 + j * 4);
        }
        #pragma unroll
        for (int i = 0; i < 8; ++i) {
            int v = tid + i * 256;
            int row = v >> 3, j = v & 7;
            cp16(smem_u32(Bs + row * PB + j * 4),
                 Bgm + (size_t)row * b_ld + k0 + j * 4);
        }
    };

    // prologue: 2 stages in flight
    load_stage(0);
    asm volatile("cp.async.commit_group;" ::: "memory");
    load_stage(1);
    asm volatile("cp.async.commit_group;" ::: "memory");

    for (int s = 0; s < nstages; ++s) {
        asm volatile("cp.async.wait_group 1;" ::: "memory");   // stage s resident
        __syncthreads();   // all warps done with stage s-1 (same buffer as s+2)

        if (s + 2 < nstages) load_stage(s + 2);
        asm volatile("cp.async.commit_group;" ::: "memory");   // uniform group count

        const int buf = s % NSTAGE;
        const float* As = sm + buf * STAGE_FLOATS;
        const float* Bs = As + A_SM_FLOATS;
        const float* Abase = As + (wm * 64 + g) * PA + t;
        const float* Bbase = Bs + (wn * 64 + g) * PB + 2 * t;

        #pragma unroll
        for (int kk = 0; kk < KC; kk += 8) {
            float2 bv[8];
            #pragma unroll
            for (int ni = 0; ni < 8; ++ni)
                bv[ni] = *reinterpret_cast<const float2*>(Bbase + ni * 8 * PB + kk);
            #pragma unroll
            for (int mi = 0; mi < 4; ++mi) {
                const float* p = Abase + mi * 16 * PA + kk;
                uint32_t a[4];
                a[0] = __float_as_uint(p[0]);
                a[1] = __float_as_uint(p[8 * PA]);
                a[2] = __float_as_uint(p[4]);
                a[3] = __float_as_uint(p[8 * PA + 4]);
                #pragma unroll
                for (int ni = 0; ni < 8; ++ni)
                    mma_tf32(acc[mi][ni], a,
                             __float_as_uint(bv[ni].x), __float_as_uint(bv[ni].y));
            }
        }
    }

    // ---- epilogue ----
    const int mbase = mtile * TILE_M + wm * 64;
    const int nbase = ntile * TILE_N + wn * 64;
    const int pg = kperm8(g);   // permuted within-8-block row offset

    if (mode == 0) {
        #pragma unroll
        for (int mi = 0; mi < 4; ++mi) {
            int r0p = mbase + mi * 16 + pg;   // (mbase+mi*16) is 8-aligned
            int r1p = r0p + 8;
            #pragma unroll
            for (int ni = 0; ni < 8; ++ni) {
                int c0 = nbase + ni * 8 + 2 * t;
                int c1 = c0 + 1;
                g_gT[(size_t)c0 * NROWS + r0p] = rna_tf32(acc[mi][ni][0]);
                g_gT[(size_t)c1 * NROWS + r0p] = rna_tf32(acc[mi][ni][1]);
                g_gT[(size_t)c0 * NROWS + r1p] = rna_tf32(acc[mi][ni][2]);
                g_gT[(size_t)c1 * NROWS + r1p] = rna_tf32(acc[mi][ni][3]);
            }
        }
    } else {
        #pragma unroll
        for (int mi = 0; mi < 4; ++mi) {
            int r0 = mbase + mi * 16 + g;     // logical output row
            int r1 = r0 + 8;
            int r0p = mbase + mi * 16 + pg;   // permuted gT column
            int r1p = r0p + 8;
            float h0 = __ldg(hat_d + r0);
            float h1 = __ldg(hat_d + r1);
            #pragma unroll
            for (int ni = 0; ni < 8; ++ni) {
                int c0 = nbase + ni * 8 + 2 * t;
                int c1 = c0 + 1;
                float b0v = __ldg(bias + c0);
                float b1v = __ldg(bias + c1);
                float g00 = g_gT[(size_t)c0 * NROWS + r0p];
                float g01 = g_gT[(size_t)c1 * NROWS + r0p];
                float g10 = g_gT[(size_t)c0 * NROWS + r1p];
                float g11 = g_gT[(size_t)c1 * NROWS + r1p];
                float2 v0, v1;
                v0.x = fmaf(h0, acc[mi][ni][0] + g00, b0v);
                v0.y = fmaf(h0, acc[mi][ni][1] + g01, b1v);
                v1.x = fmaf(h1, acc[mi][ni][2] + g10, b0v);
                v1.y = fmaf(h1, acc[mi][ni][3] + g11, b1v);
                *reinterpret_cast<float2*>(out + (size_t)r0 * OUTF + c0) = v0;
                *reinterpret_cast<float2*>(out + (size_t)r1 * OUTF + c0) = v1;
            }
        }
    }
}

// ---------------------------------------------------------------------------
// Host side
// ---------------------------------------------------------------------------
extern "C" void kernel_launch(void* const* d_in, const int* in_sizes, int n_in,
                              void* d_out, int out_size) {
    const float *A = nullptr, *hat_d = nullptr, *feature = nullptr,
                *W = nullptr, *b = nullptr;
    for (int i = 0; i < n_in; ++i) {
        switch (in_sizes[i]) {
            case NROWS:       hat_d   = (const float*)d_in[i]; break;   // 16384
            case OUTF:        b       = (const float*)d_in[i]; break;   // 256
            case OUTF * INF:  W       = (const float*)d_in[i]; break;   // 131072
            case NROWS * INF: feature = (const float*)d_in[i]; break;   // 8388608
            default:          A       = (const float*)d_in[i]; break;   // 16384*16384
        }
    }

    void *p_dhf = nullptr, *p_wrn = nullptr, *p_gT = nullptr;
    cudaGetSymbolAddress(&p_dhf, g_dhf);
    cudaGetSymbolAddress(&p_wrn, g_wrn);
    cudaGetSymbolAddress(&p_gT,  g_gT);

    static bool attr_set = false;
    if (!attr_set) {
        cudaFuncSetAttribute(gemm_tf32_kernel,
                             cudaFuncAttributeMaxDynamicSharedMemorySize, SMEM_BYTES);
        attr_set = true;
    }

    prep_kernel<<<1024, 256>>>(hat_d, feature, W);

    // GEMM1: g^T = (dhf @ W^T)^T   K = 512 -> 16 stages  (B = wrn, kperm8)
    gemm_tf32_kernel<<<dim3(NROWS / TILE_M, OUTF / TILE_N), 256, SMEM_BYTES>>>(
        (const float*)p_dhf, INF,
        (const float*)p_wrn, INF,
        INF / KC, 0, nullptr, nullptr, nullptr);

    // GEMM2: out = hat_d*(A@g + g) + b   K = 16384 -> 512 stages  (B = gT, kperm8)
    gemm_tf32_kernel<<<dim3(NROWS / TILE_M, OUTF / TILE_N), 256, SMEM_BYTES>>>(
        A, NROWS,
        (const float*)p_gT, NROWS,
        NROWS / KC, 1, hat_d, b, (float*)d_out);

    (void)out_size;
}

// round 12
// speedup vs baseline: 1.5073x; 1.3742x over previous
#include <cuda_runtime.h>
#include <cuda_fp16.h>
#include <cstdint>
#include <cstddef>

// ---------------------------------------------------------------------------
// Problem dims
// ---------------------------------------------------------------------------
#define NROWS 16384
#define INF   512
#define OUTF  256

// GEMM tiling: CTA tile 128(M) x 256(N), warp tile 64x64, 1 CTA/SM, 3 stages
#define TILE_M 128
#define TILE_N 256
#define KC     32            // K elems per pipeline stage
#define PA     40            // A smem pitch (fp32): LDS.64 bankpair (10*row+t)&15 distinct per phase
#define PBH    40            // B smem pitch (halves): LDS.64 conflict-free per phase
#define A_SM_FLOATS (TILE_M * PA)                          // 5120 fp32 = 20480 B
#define B_SM_HALVES (TILE_N * PBH)                         // 10240 half = 20480 B
#define STAGE_BYTES (A_SM_FLOATS * 4 + B_SM_HALVES * 2)    // 40960
#define NSTAGE 3
#define SMEM_BYTES (NSTAGE * STAGE_BYTES)                  // 122880

// within-16-block k permutation for fp16 B operands:
//   logical k -> phys = 4*((k>>1)&3) + 2*((k>>3)&1) + (k&1)
// => thread t's m16n8k16 B halves {2t,2t+1,2t+8,2t+9} land at phys [4t..4t+3] (one LDS.64)
__host__ __device__ __forceinline__ int perm16(int k) {
    return 4 * ((k >> 1) & 3) + 2 * ((k >> 3) & 1) + (k & 1);
}

// ---------------------------------------------------------------------------
// Scratch (__device__ globals: allocation-free)
// ---------------------------------------------------------------------------
__device__ __align__(256) float  g_dhf[(size_t)NROWS * INF];   // hat_d*feature (fp32)
__device__ __align__(256) __half g_wrn[(size_t)OUTF * INF];    // W, fp16 rna, perm16 k-layout
__device__ __align__(256) __half g_gT [(size_t)OUTF * NROWS];  // g^T, fp16 rna, perm16 k-layout

// ---------------------------------------------------------------------------
// Helpers
// ---------------------------------------------------------------------------
__device__ __forceinline__ uint32_t smem_u32(const void* p) {
    uint32_t a;
    asm("{ .reg .u64 t; cvta.to.shared.u64 t, %1; cvt.u32.u64 %0, t; }" : "=r"(a) : "l"(p));
    return a;
}

__device__ __forceinline__ void cp16(uint32_t dst_smem, const void* src) {
    asm volatile("cp.async.cg.shared.global [%0], [%1], 16;"
                 :: "r"(dst_smem), "l"(src) : "memory");
}

__device__ __forceinline__ uint32_t f2h2(float lo, float hi) {
    uint32_t r;
    asm("cvt.rn.f16x2.f32 %0, %2, %1;" : "=r"(r) : "f"(lo), "f"(hi));
    return r;
}

__device__ __forceinline__ void mma_f16(float* d, const uint32_t* a, uint32_t b0, uint32_t b1) {
    asm volatile(
        "mma.sync.aligned.m16n8k16.row.col.f32.f16.f16.f32 "
        "{%0,%1,%2,%3}, {%4,%5,%6,%7}, {%8,%9}, {%0,%1,%2,%3};"
        : "+f"(d[0]), "+f"(d[1]), "+f"(d[2]), "+f"(d[3])
        : "r"(a[0]), "r"(a[1]), "r"(a[2]), "r"(a[3]),
          "r"(b0), "r"(b1));
}

// ---------------------------------------------------------------------------
// Prep: dhf = hat_d * feature (fp32);  wrn[r][perm16(k)] = half_rn(W[r][k])
// ---------------------------------------------------------------------------
__global__ void prep_kernel(const float* __restrict__ hat_d,
                            const float* __restrict__ feature,
                            const float* __restrict__ W) {
    size_t i = (size_t)blockIdx.x * blockDim.x + threadIdx.x;
    size_t stride = (size_t)gridDim.x * blockDim.x;

    const float4* f4 = reinterpret_cast<const float4*>(feature);
    float4* d4 = reinterpret_cast<float4*>(g_dhf);
    size_t total4 = (size_t)NROWS * INF / 4;
    for (size_t idx = i; idx < total4; idx += stride) {
        float4 f = f4[idx];
        float d = __ldg(hat_d + (idx >> 7));
        float4 o;
        o.x = d * f.x;
        o.y = d * f.y;
        o.z = d * f.z;
        o.w = d * f.w;
        d4[idx] = o;
    }

    size_t wtotal = (size_t)OUTF * INF;
    for (size_t idx = i; idx < wtotal; idx += stride) {
        int k = (int)(idx & (INF - 1));
        size_t row = idx >> 9;
        int kp = (k & ~15) | perm16(k & 15);
        g_wrn[row * INF + kp] = __float2half_rn(W[idx]);
    }
}

// ---------------------------------------------------------------------------
// fp16 mma.sync GEMM: D[128 x 256] = Afp32[128 x K] @ Bfp16[256 x K]^T
//   A fp32 in gmem/smem, converted to fp16 (rna) at fragment load.
//   B fp16 in gmem with perm16 k-layout.
//   mode 0: g_gT[n][perm16-scattered m] = half_rn(D[m][n])        (GEMM1)
//   mode 1: out[m][n] = hat_d[m]*(D[m][n] + gT_perm[n][m]) + b[n] (GEMM2)
// 256 threads = 8 warps in 2(M) x 4(N); warp tile 64 x 64; 1 CTA/SM.
// ---------------------------------------------------------------------------
__global__ void __launch_bounds__(256, 1)
gemm_f16_kernel(const float* __restrict__ Ap, int a_ld,
                const __half* __restrict__ Bp, int b_ld,
                int nstages, int mode,
                const float* __restrict__ hat_d,
                const float* __restrict__ bias,
                float* __restrict__ out)
{
    extern __shared__ char smraw[];
    const int tid = threadIdx.x;
    const int mtile = blockIdx.x;
    const int ntile = blockIdx.y;
    const int wid = tid >> 5;
    const int lane = tid & 31;
    const int wm = wid & 1;           // 0..1: M position (64 rows each)
    const int wn = wid >> 1;          // 0..3: N position (64 cols each)
    const int g = lane >> 2;          // groupID 0..7
    const int t = lane & 3;           // threadID in group 0..3

    float acc[4][8][4];
    #pragma unroll
    for (int mi = 0; mi < 4; ++mi)
        #pragma unroll
        for (int ni = 0; ni < 8; ++ni)
            #pragma unroll
            for (int r = 0; r < 4; ++r)
                acc[mi][ni][r] = 0.0f;

    const float*  Agm = Ap + (size_t)mtile * TILE_M * a_ld;
    const __half* Bgm = Bp + (size_t)ntile * TILE_N * b_ld;

    // ---- stage loader: A 128 rows x 8 chunks fp32; B 256 rows x 4 chunks fp16 ----
    auto load_stage = [&](int s) {
        const int buf = s % NSTAGE;
        float*  As = reinterpret_cast<float*>(smraw + buf * STAGE_BYTES);
        __half* Bs = reinterpret_cast<__half*>(smraw + buf * STAGE_BYTES + A_SM_FLOATS * 4);
        const int k0 = s * KC;
        #pragma unroll
        for (int i = 0; i < 4; ++i) {                 // A: 1024 chunks
            int v = tid + i * 256;
            int row = v >> 3, j = v & 7;
            cp16(smem_u32(As + row * PA + j * 4),
                 Agm + (size_t)row * a_ld + k0 + j * 4);
        }
        #pragma unroll
        for (int i = 0; i < 4; ++i) {                 // B: 1024 chunks (8 halves each)
            int v = tid + i * 256;
            int row = v >> 2, j = v & 3;
            cp16(smem_u32(Bs + row * PBH + j * 8),
                 Bgm + (size_t)row * b_ld + k0 + j * 8);
        }
    };

    // prologue: 2 stages in flight
    load_stage(0);
    asm volatile("cp.async.commit_group;" ::: "memory");
    load_stage(1);
    asm volatile("cp.async.commit_group;" ::: "memory");

    for (int s = 0; s < nstages; ++s) {
        asm volatile("cp.async.wait_group 1;" ::: "memory");   // stage s resident
        __syncthreads();   // all warps done with buffer being refilled next

        if (s + 2 < nstages) load_stage(s + 2);
        asm volatile("cp.async.commit_group;" ::: "memory");   // uniform group count

        const int buf = s % NSTAGE;
        const float*  As = reinterpret_cast<const float*>(smraw + buf * STAGE_BYTES);
        const __half* Bs = reinterpret_cast<const __half*>(smraw + buf * STAGE_BYTES + A_SM_FLOATS * 4);
        const float*  Abase = As + (wm * 64 + g) * PA + 2 * t;
        const __half* Bbase = Bs + (wn * 64 + g) * PBH + 4 * t;

        #pragma unroll
        for (int kk = 0; kk < 2; ++kk) {              // two k16 steps per stage
            // B fragments: one LDS.64 per ni (perm16 layout -> halves {2t,2t+1,2t+8,2t+9})
            uint2 bv[8];
            #pragma unroll
            for (int ni = 0; ni < 8; ++ni)
                bv[ni] = *reinterpret_cast<const uint2*>(Bbase + ni * 8 * PBH + kk * 16);

            #pragma unroll
            for (int mi = 0; mi < 4; ++mi) {
                const float* p = Abase + mi * 16 * PA + kk * 16;
                float2 x0 = *reinterpret_cast<const float2*>(p);                 // A[g][2t,2t+1]
                float2 x1 = *reinterpret_cast<const float2*>(p + 8 * PA);        // A[g+8][2t,2t+1]
                float2 x2 = *reinterpret_cast<const float2*>(p + 8);             // A[g][2t+8,2t+9]
                float2 x3 = *reinterpret_cast<const float2*>(p + 8 * PA + 8);    // A[g+8][2t+8,2t+9]
                uint32_t a[4];
                a[0] = f2h2(x0.x, x0.y);
                a[1] = f2h2(x1.x, x1.y);
                a[2] = f2h2(x2.x, x2.y);
                a[3] = f2h2(x3.x, x3.y);
                #pragma unroll
                for (int ni = 0; ni < 8; ++ni)
                    mma_f16(acc[mi][ni], a, bv[ni].x, bv[ni].y);
            }
        }
    }

    // ---- epilogue ----
    // m within its 16-block: logical g -> perm16 pos pg0 = 4*(g>>1)+(g&1); g+8 -> pg0+2
    const int mbase = mtile * TILE_M + wm * 64;
    const int nbase = ntile * TILE_N + wn * 64;
    const int pg = 4 * (g >> 1) + (g & 1);

    if (mode == 0) {
        #pragma unroll
        for (int mi = 0; mi < 4; ++mi) {
            int r0p = mbase + mi * 16 + pg;   // (mbase+mi*16) is 16-aligned
            int r1p = r0p + 2;
            #pragma unroll
            for (int ni = 0; ni < 8; ++ni) {
                int c0 = nbase + ni * 8 + 2 * t;
                int c1 = c0 + 1;
                g_gT[(size_t)c0 * NROWS + r0p] = __float2half_rn(acc[mi][ni][0]);
                g_gT[(size_t)c1 * NROWS + r0p] = __float2half_rn(acc[mi][ni][1]);
                g_gT[(size_t)c0 * NROWS + r1p] = __float2half_rn(acc[mi][ni][2]);
                g_gT[(size_t)c1 * NROWS + r1p] = __float2half_rn(acc[mi][ni][3]);
            }
        }
    } else {
        #pragma unroll
        for (int mi = 0; mi < 4; ++mi) {
            int r0 = mbase + mi * 16 + g;     // logical output row
            int r1 = r0 + 8;
            int r0p = mbase + mi * 16 + pg;   // permuted gT column
            int r1p = r0p + 2;
            float h0 = __ldg(hat_d + r0);
            float h1 = __ldg(hat_d + r1);
            #pragma unroll
            for (int ni = 0; ni < 8; ++ni) {
                int c0 = nbase + ni * 8 + 2 * t;
                int c1 = c0 + 1;
                float b0v = __ldg(bias + c0);
                float b1v = __ldg(bias + c1);
                float g00 = __half2float(g_gT[(size_t)c0 * NROWS + r0p]);
                float g01 = __half2float(g_gT[(size_t)c1 * NROWS + r0p]);
                float g10 = __half2float(g_gT[(size_t)c0 * NROWS + r1p]);
                float g11 = __half2float(g_gT[(size_t)c1 * NROWS + r1p]);
                float2 v0, v1;
                v0.x = fmaf(h0, acc[mi][ni][0] + g00, b0v);
                v0.y = fmaf(h0, acc[mi][ni][1] + g01, b1v);
                v1.x = fmaf(h1, acc[mi][ni][2] + g10, b0v);
                v1.y = fmaf(h1, acc[mi][ni][3] + g11, b1v);
                *reinterpret_cast<float2*>(out + (size_t)r0 * OUTF + c0) = v0;
                *reinterpret_cast<float2*>(out + (size_t)r1 * OUTF + c0) = v1;
            }
        }
    }
}

// ---------------------------------------------------------------------------
// Host side
// ---------------------------------------------------------------------------
extern "C" void kernel_launch(void* const* d_in, const int* in_sizes, int n_in,
                              void* d_out, int out_size) {
    const float *A = nullptr, *hat_d = nullptr, *feature = nullptr,
                *W = nullptr, *b = nullptr;
    for (int i = 0; i < n_in; ++i) {
        switch (in_sizes[i]) {
            case NROWS:       hat_d   = (const float*)d_in[i]; break;   // 16384
            case OUTF:        b       = (const float*)d_in[i]; break;   // 256
            case OUTF * INF:  W       = (const float*)d_in[i]; break;   // 131072
            case NROWS * INF: feature = (const float*)d_in[i]; break;   // 8388608
            default:          A       = (const float*)d_in[i]; break;   // 16384*16384
        }
    }

    void *p_dhf = nullptr, *p_wrn = nullptr, *p_gT = nullptr;
    cudaGetSymbolAddress(&p_dhf, g_dhf);
    cudaGetSymbolAddress(&p_wrn, g_wrn);
    cudaGetSymbolAddress(&p_gT,  g_gT);

    static bool attr_set = false;
    if (!attr_set) {
        cudaFuncSetAttribute(gemm_f16_kernel,
                             cudaFuncAttributeMaxDynamicSharedMemorySize, SMEM_BYTES);
        attr_set = true;
    }

    prep_kernel<<<1024, 256>>>(hat_d, feature, W);

    // GEMM1: g^T = (dhf @ W^T)^T   K = 512 -> 16 stages  (B = wrn fp16, perm16)
    gemm_f16_kernel<<<dim3(NROWS / TILE_M, OUTF / TILE_N), 256, SMEM_BYTES>>>(
        (const float*)p_dhf, INF,
        (const __half*)p_wrn, INF,
        INF / KC, 0, nullptr, nullptr, nullptr);

    // GEMM2: out = hat_d*(A@g + g) + b   K = 16384 -> 512 stages  (B = gT fp16, perm16)
    gemm_f16_kernel<<<dim3(NROWS / TILE_M, OUTF / TILE_N), 256, SMEM_BYTES>>>(
        A, NROWS,
        (const __half*)p_gT, NROWS,
        NROWS / KC, 1, hat_d, b, (float*)d_out);

    (void)out_size;
}

// round 13
// speedup vs baseline: 1.6581x; 1.1000x over previous
#include <cuda_runtime.h>
#include <cuda_fp16.h>
#include <cstdint>
#include <cstddef>

// ---------------------------------------------------------------------------
// Problem dims
// ---------------------------------------------------------------------------
#define NROWS 16384
#define INF   512
#define OUTF  256

// GEMM tiling: CTA tile 128(M) x 256(N), warp tile 64x64, 1 CTA/SM, 3 stages
#define TILE_M 128
#define TILE_N 256
#define KC     32            // K elems per pipeline stage (2 k16 blocks)
#define PH     48            // smem pitch in halves for A and B tiles (96B)
#define A_SM_HALVES (TILE_M * PH)                    // 6144 -> 12288 B
#define B_SM_HALVES (TILE_N * PH)                    // 12288 -> 24576 B
#define STAGE_BYTES ((A_SM_HALVES + B_SM_HALVES) * 2)  // 36864
#define NSTAGE 3
#define SMEM_BYTES (NSTAGE * STAGE_BYTES)            // 110592

// within-16-block k permutation for fp16 operands:
//   logical k -> phys = 4*((k>>1)&3) + 2*((k>>3)&1) + (k&1)
// => thread t's m16n8k16 halves {2t,2t+1,2t+8,2t+9} land at phys [4t..4t+3] (one LDS.64)
__host__ __device__ __forceinline__ int perm16(int k) {
    return 4 * ((k >> 1) & 3) + 2 * ((k >> 3) & 1) + (k & 1);
}

// ---------------------------------------------------------------------------
// Scratch (__device__ globals: allocation-free)
// ---------------------------------------------------------------------------
__device__ __align__(256) float  g_dhf[(size_t)NROWS * INF];   // hat_d*feature (fp32)
__device__ __align__(256) __half g_wrn[(size_t)OUTF * INF];    // W, fp16 rn, perm16 k-layout
__device__ __align__(256) __half g_gT [(size_t)OUTF * NROWS];  // g^T, fp16 rn, perm16 k-layout

// ---------------------------------------------------------------------------
// Helpers
// ---------------------------------------------------------------------------
__device__ __forceinline__ uint32_t smem_u32(const void* p) {
    uint32_t a;
    asm("{ .reg .u64 t; cvta.to.shared.u64 t, %1; cvt.u32.u64 %0, t; }" : "=r"(a) : "l"(p));
    return a;
}

__device__ __forceinline__ void cp16(uint32_t dst_smem, const void* src) {
    asm volatile("cp.async.cg.shared.global [%0], [%1], 16;"
                 :: "r"(dst_smem), "l"(src) : "memory");
}

__device__ __forceinline__ uint32_t f2h2(float lo, float hi) {
    uint32_t r;
    asm("cvt.rn.f16x2.f32 %0, %2, %1;" : "=r"(r) : "f"(lo), "f"(hi));
    return r;
}

__device__ __forceinline__ void mma_f16(float* d, const uint32_t* a, uint32_t b0, uint32_t b1) {
    asm volatile(
        "mma.sync.aligned.m16n8k16.row.col.f32.f16.f16.f32 "
        "{%0,%1,%2,%3}, {%4,%5,%6,%7}, {%8,%9}, {%0,%1,%2,%3};"
        : "+f"(d[0]), "+f"(d[1]), "+f"(d[2]), "+f"(d[3])
        : "r"(a[0]), "r"(a[1]), "r"(a[2]), "r"(a[3]),
          "r"(b0), "r"(b1));
}

// ---------------------------------------------------------------------------
// Prep: dhf = hat_d * feature (fp32);  wrn[r][perm16(k)] = half_rn(W[r][k])
// ---------------------------------------------------------------------------
__global__ void prep_kernel(const float* __restrict__ hat_d,
                            const float* __restrict__ feature,
                            const float* __restrict__ W) {
    size_t i = (size_t)blockIdx.x * blockDim.x + threadIdx.x;
    size_t stride = (size_t)gridDim.x * blockDim.x;

    const float4* f4 = reinterpret_cast<const float4*>(feature);
    float4* d4 = reinterpret_cast<float4*>(g_dhf);
    size_t total4 = (size_t)NROWS * INF / 4;
    for (size_t idx = i; idx < total4; idx += stride) {
        float4 f = f4[idx];
        float d = __ldg(hat_d + (idx >> 7));
        float4 o;
        o.x = d * f.x;
        o.y = d * f.y;
        o.z = d * f.z;
        o.w = d * f.w;
        d4[idx] = o;
    }

    size_t wtotal = (size_t)OUTF * INF;
    for (size_t idx = i; idx < wtotal; idx += stride) {
        int k = (int)(idx & (INF - 1));
        size_t row = idx >> 9;
        int kp = (k & ~15) | perm16(k & 15);
        g_wrn[row * INF + kp] = __float2half_rn(W[idx]);
    }
}

// ---------------------------------------------------------------------------
// fp16 mma.sync GEMM: D[128 x 256] = Afp32[128 x K] @ Bfp16[256 x K]^T
//   A fp32 in gmem, converted to fp16 (rn) via LDG->cvt->STS into perm16 smem.
//   B fp16 in gmem with perm16 k-layout, staged via cp.async.
//   mode 0: g_gT[n][perm16-scattered m] = half_rn(D[m][n])        (GEMM1)
//   mode 1: out[m][n] = hat_d[m]*(D[m][n] + gT_perm[n][m]) + b[n] (GEMM2)
// 256 threads = 8 warps in 2(M) x 4(N); warp tile 64 x 64; 1 CTA/SM.
// ---------------------------------------------------------------------------
__global__ void __launch_bounds__(256, 1)
gemm_f16_kernel(const float* __restrict__ Ap, int a_ld,
                const __half* __restrict__ Bp, int b_ld,
                int nstages, int mode,
                const float* __restrict__ hat_d,
                const float* __restrict__ bias,
                float* __restrict__ out)
{
    extern __shared__ char smraw[];
    const int tid = threadIdx.x;
    const int mtile = blockIdx.x;
    const int ntile = blockIdx.y;
    const int wid = tid >> 5;
    const int lane = tid & 31;
    const int wm = wid & 1;           // 0..1: M position (64 rows each)
    const int wn = wid >> 1;          // 0..3: N position (64 cols each)
    const int g = lane >> 2;          // groupID 0..7
    const int t = lane & 3;           // threadID in group 0..3

    float acc[4][8][4];
    #pragma unroll
    for (int mi = 0; mi < 4; ++mi)
        #pragma unroll
        for (int ni = 0; ni < 8; ++ni)
            #pragma unroll
            for (int r = 0; r < 4; ++r)
                acc[mi][ni][r] = 0.0f;

    const float*  Agm = Ap + (size_t)mtile * TILE_M * a_ld;
    const __half* Bgm = Bp + (size_t)ntile * TILE_N * b_ld;

    // A staging: thread v owns (row = v>>1, kblock = v&1); 16 consecutive fp32.
    const int a_row = tid >> 1;
    const int a_kb  = tid & 1;
    const float* a_src_base = Agm + (size_t)a_row * a_ld + a_kb * 16;
    float a_stage[16];

    auto ldgA = [&](int s) {
        const float* p = a_src_base + s * KC;
        #pragma unroll
        for (int i = 0; i < 4; ++i) {
            float4 v = __ldg(reinterpret_cast<const float4*>(p + 4 * i));
            a_stage[4 * i + 0] = v.x;
            a_stage[4 * i + 1] = v.y;
            a_stage[4 * i + 2] = v.z;
            a_stage[4 * i + 3] = v.w;
        }
    };
    // cvt + store into perm16 smem layout:
    //   word w[2q+h] = (half(k[2q+8h]), half(k[2q+8h+1]))   q=0..3, h=0..1
    auto stsA = [&](int s) {
        __half* As = reinterpret_cast<__half*>(smraw + (s % NSTAGE) * STAGE_BYTES);
        uint32_t w[8];
        #pragma unroll
        for (int q = 0; q < 4; ++q) {
            w[2 * q + 0] = f2h2(a_stage[2 * q + 0], a_stage[2 * q + 1]);
            w[2 * q + 1] = f2h2(a_stage[2 * q + 8], a_stage[2 * q + 9]);
        }
        uint32_t dst = smem_u32(As + a_row * PH + a_kb * 16);
        asm volatile("st.shared.v4.b32 [%0], {%1,%2,%3,%4};"
                     :: "r"(dst), "r"(w[0]), "r"(w[1]), "r"(w[2]), "r"(w[3]) : "memory");
        asm volatile("st.shared.v4.b32 [%0], {%1,%2,%3,%4};"
                     :: "r"(dst + 16), "r"(w[4]), "r"(w[5]), "r"(w[6]), "r"(w[7]) : "memory");
    };
    // B loader: 256 rows x 2 chunks(16B) per kblock -> 1024 cp16 across 256 threads
    auto cpB = [&](int s) {
        __half* Bs = reinterpret_cast<__half*>(smraw + (s % NSTAGE) * STAGE_BYTES) + A_SM_HALVES;
        const int k0 = s * KC;
        #pragma unroll
        for (int i = 0; i < 4; ++i) {
            int v = tid + i * 256;
            int row = v >> 2, j = v & 3;
            cp16(smem_u32(Bs + row * PH + j * 8),
                 Bgm + (size_t)row * b_ld + k0 + j * 8);
        }
    };

    // ---- prologue: A(0) stored, A(1) in regs, B(0)/B(1) in flight ----
    ldgA(0);
    stsA(0);
    ldgA(1);
    cpB(0);
    asm volatile("cp.async.commit_group;" ::: "memory");
    cpB(1);
    asm volatile("cp.async.commit_group;" ::: "memory");

    for (int s = 0; s < nstages; ++s) {
        asm volatile("cp.async.wait_group 1;" ::: "memory");   // B(s) resident
        __syncthreads();   // compute(s-1) done; A(s) STS visible

        if (s + 1 < nstages) stsA(s + 1);
        if (s + 2 < nstages) { cpB(s + 2); ldgA(s + 2); }
        asm volatile("cp.async.commit_group;" ::: "memory");   // uniform group count

        const __half* As = reinterpret_cast<const __half*>(smraw + (s % NSTAGE) * STAGE_BYTES);
        const __half* Bs = As + A_SM_HALVES;
        const __half* Abase = As + (wm * 64 + g) * PH + 4 * t;
        const __half* Bbase = Bs + (wn * 64 + g) * PH + 4 * t;

        #pragma unroll
        for (int kk = 0; kk < 2; ++kk) {              // two k16 steps per stage
            uint2 bv[8];
            #pragma unroll
            for (int ni = 0; ni < 8; ++ni)
                bv[ni] = *reinterpret_cast<const uint2*>(Bbase + ni * 8 * PH + kk * 16);

            #pragma unroll
            for (int mi = 0; mi < 4; ++mi) {
                const __half* p = Abase + mi * 16 * PH + kk * 16;
                uint2 lo = *reinterpret_cast<const uint2*>(p);             // row g
                uint2 hi = *reinterpret_cast<const uint2*>(p + 8 * PH);    // row g+8
                uint32_t a[4];
                a[0] = lo.x;   // (k2t, k2t+1)   row g
                a[1] = hi.x;   // row g+8
                a[2] = lo.y;   // (k2t+8, k2t+9) row g
                a[3] = hi.y;   // row g+8
                #pragma unroll
                for (int ni = 0; ni < 8; ++ni)
                    mma_f16(acc[mi][ni], a, bv[ni].x, bv[ni].y);
            }
        }
    }

    // ---- epilogue ----
    // m within its 16-block: logical g -> perm16 pos pg = 4*(g>>1)+(g&1); g+8 -> pg+2
    const int mbase = mtile * TILE_M + wm * 64;
    const int nbase = ntile * TILE_N + wn * 64;
    const int pg = 4 * (g >> 1) + (g & 1);

    if (mode == 0) {
        #pragma unroll
        for (int mi = 0; mi < 4; ++mi) {
            int r0p = mbase + mi * 16 + pg;   // (mbase+mi*16) is 16-aligned
            int r1p = r0p + 2;
            #pragma unroll
            for (int ni = 0; ni < 8; ++ni) {
                int c0 = nbase + ni * 8 + 2 * t;
                int c1 = c0 + 1;
                g_gT[(size_t)c0 * NROWS + r0p] = __float2half_rn(acc[mi][ni][0]);
                g_gT[(size_t)c1 * NROWS + r0p] = __float2half_rn(acc[mi][ni][1]);
                g_gT[(size_t)c0 * NROWS + r1p] = __float2half_rn(acc[mi][ni][2]);
                g_gT[(size_t)c1 * NROWS + r1p] = __float2half_rn(acc[mi][ni][3]);
            }
        }
    } else {
        #pragma unroll
        for (int mi = 0; mi < 4; ++mi) {
            int r0 = mbase + mi * 16 + g;     // logical output row
            int r1 = r0 + 8;
            int r0p = mbase + mi * 16 + pg;   // permuted gT column
            int r1p = r0p + 2;
            float h0 = __ldg(hat_d + r0);
            float h1 = __ldg(hat_d + r1);
            #pragma unroll
            for (int ni = 0; ni < 8; ++ni) {
                int c0 = nbase + ni * 8 + 2 * t;
                int c1 = c0 + 1;
                float b0v = __ldg(bias + c0);
                float b1v = __ldg(bias + c1);
                float g00 = __half2float(g_gT[(size_t)c0 * NROWS + r0p]);
                float g01 = __half2float(g_gT[(size_t)c1 * NROWS + r0p]);
                float g10 = __half2float(g_gT[(size_t)c0 * NROWS + r1p]);
                float g11 = __half2float(g_gT[(size_t)c1 * NROWS + r1p]);
                float2 v0, v1;
                v0.x = fmaf(h0, acc[mi][ni][0] + g00, b0v);
                v0.y = fmaf(h0, acc[mi][ni][1] + g01, b1v);
                v1.x = fmaf(h1, acc[mi][ni][2] + g10, b0v);
                v1.y = fmaf(h1, acc[mi][ni][3] + g11, b1v);
                *reinterpret_cast<float2*>(out + (size_t)r0 * OUTF + c0) = v0;
                *reinterpret_cast<float2*>(out + (size_t)r1 * OUTF + c0) = v1;
            }
        }
    }
}

// ---------------------------------------------------------------------------
// Host side
// ---------------------------------------------------------------------------
extern "C" void kernel_launch(void* const* d_in, const int* in_sizes, int n_in,
                              void* d_out, int out_size) {
    const float *A = nullptr, *hat_d = nullptr, *feature = nullptr,
                *W = nullptr, *b = nullptr;
    for (int i = 0; i < n_in; ++i) {
        switch (in_sizes[i]) {
            case NROWS:       hat_d   = (const float*)d_in[i]; break;   // 16384
            case OUTF:        b       = (const float*)d_in[i]; break;   // 256
            case OUTF * INF:  W       = (const float*)d_in[i]; break;   // 131072
            case NROWS * INF: feature = (const float*)d_in[i]; break;   // 8388608
            default:          A       = (const float*)d_in[i]; break;   // 16384*16384
        }
    }

    void *p_dhf = nullptr, *p_wrn = nullptr, *p_gT = nullptr;
    cudaGetSymbolAddress(&p_dhf, g_dhf);
    cudaGetSymbolAddress(&p_wrn, g_wrn);
    cudaGetSymbolAddress(&p_gT,  g_gT);

    static bool attr_set = false;
    if (!attr_set) {
        cudaFuncSetAttribute(gemm_f16_kernel,
                             cudaFuncAttributeMaxDynamicSharedMemorySize, SMEM_BYTES);
        attr_set = true;
    }

    prep_kernel<<<1024, 256>>>(hat_d, feature, W);

    // GEMM1: g^T = (dhf @ W^T)^T   K = 512 -> 16 stages  (B = wrn fp16, perm16)
    gemm_f16_kernel<<<dim3(NROWS / TILE_M, OUTF / TILE_N), 256, SMEM_BYTES>>>(
        (const float*)p_dhf, INF,
        (const __half*)p_wrn, INF,
        INF / KC, 0, nullptr, nullptr, nullptr);

    // GEMM2: out = hat_d*(A@g + g) + b   K = 16384 -> 512 stages  (B = gT fp16, perm16)
    gemm_f16_kernel<<<dim3(NROWS / TILE_M, OUTF / TILE_N), 256, SMEM_BYTES>>>(
        A, NROWS,
        (const __half*)p_gT, NROWS,
        NROWS / KC, 1, hat_d, b, (float*)d_out);

    (void)out_size;
}

// round 14
// speedup vs baseline: 1.8278x; 1.1023x over previous
#include <cuda_runtime.h>
#include <cuda_fp16.h>
#include <cstdint>
#include <cstddef>

// ---------------------------------------------------------------------------
// Problem dims
// ---------------------------------------------------------------------------
#define NROWS 16384
#define INF   512
#define OUTF  256

#define PH    48             // smem pitch in halves (96 B) for all fp16 tiles
#define KC    32             // K elems per pipeline stage (2 k16 blocks)
#define NSTAGE 3

// ---- GEMM1 tiling (128 x 256, unchanged skeleton) ----
#define G1_TILE_M 128
#define G1_A_HALVES (G1_TILE_M * PH)                 // 6144
#define G1_B_HALVES (OUTF * PH)                      // 12288
#define G1_STAGE_BYTES ((G1_A_HALVES + G1_B_HALVES) * 2)   // 36864
#define G1_SMEM (NSTAGE * G1_STAGE_BYTES)            // 110592

// ---- GEMM2 tiling (112 x 256 per CTA, 148 CTAs) ----
#define G2_TILE_M 112                                // 7 x 16-row blocks
#define G2_NMI    7
#define G2_A_HALVES (G2_TILE_M * PH)                 // 5376
#define G2_B_HALVES (OUTF * PH)                      // 12288
#define G2_STAGE_BYTES ((G2_A_HALVES + G2_B_HALVES) * 2)   // 35328
#define G2_SMEM (NSTAGE * G2_STAGE_BYTES)            // 105984
#define NCTA2 148
#define MBLOCKS (NROWS / 16)                         // 1024

// within-16-block k permutation for fp16 operands:
//   logical k -> phys = 4*((k>>1)&3) + 2*((k>>3)&1) + (k&1)
// => thread t's m16n8k16 halves {2t,2t+1,2t+8,2t+9} land at phys [4t..4t+3] (one LDS.64)
__host__ __device__ __forceinline__ int perm16(int k) {
    return 4 * ((k >> 1) & 3) + 2 * ((k >> 3) & 1) + (k & 1);
}

// ---------------------------------------------------------------------------
// Scratch (__device__ globals: allocation-free)
// ---------------------------------------------------------------------------
__device__ __align__(256) __half g_wrn[(size_t)OUTF * INF];    // W, fp16 rn, perm16 k-layout
__device__ __align__(256) __half g_gT [(size_t)OUTF * NROWS];  // g^T, fp16 rn, perm16 k-layout

// ---------------------------------------------------------------------------
// Helpers
// ---------------------------------------------------------------------------
__device__ __forceinline__ uint32_t smem_u32(const void* p) {
    uint32_t a;
    asm("{ .reg .u64 t; cvta.to.shared.u64 t, %1; cvt.u32.u64 %0, t; }" : "=r"(a) : "l"(p));
    return a;
}

__device__ __forceinline__ void cp16(uint32_t dst_smem, const void* src) {
    asm volatile("cp.async.cg.shared.global [%0], [%1], 16;"
                 :: "r"(dst_smem), "l"(src) : "memory");
}

__device__ __forceinline__ uint32_t f2h2(float lo, float hi) {
    uint32_t r;
    asm("cvt.rn.f16x2.f32 %0, %2, %1;" : "=r"(r) : "f"(lo), "f"(hi));
    return r;
}

__device__ __forceinline__ void mma_f16(float* d, const uint32_t* a, uint32_t b0, uint32_t b1) {
    asm volatile(
        "mma.sync.aligned.m16n8k16.row.col.f32.f16.f16.f32 "
        "{%0,%1,%2,%3}, {%4,%5,%6,%7}, {%8,%9}, {%0,%1,%2,%3};"
        : "+f"(d[0]), "+f"(d[1]), "+f"(d[2]), "+f"(d[3])
        : "r"(a[0]), "r"(a[1]), "r"(a[2]), "r"(a[3]),
          "r"(b0), "r"(b1));
}

// ---------------------------------------------------------------------------
// Prep: wrn[r][perm16(k)] = half_rn(W[r][k])   (W only; dh fused into GEMM1)
// ---------------------------------------------------------------------------
__global__ void prep_w_kernel(const float* __restrict__ W) {
    size_t i = (size_t)blockIdx.x * blockDim.x + threadIdx.x;
    size_t stride = (size_t)gridDim.x * blockDim.x;
    size_t wtotal = (size_t)OUTF * INF;
    for (size_t idx = i; idx < wtotal; idx += stride) {
        int k = (int)(idx & (INF - 1));
        size_t row = idx >> 9;
        int kp = (k & ~15) | perm16(k & 15);
        g_wrn[row * INF + kp] = __float2half_rn(W[idx]);
    }
}

// ---------------------------------------------------------------------------
// GEMM1: g^T = ((hat_d .* feature) @ W^T)^T, fp16 MMA.
//   A = feature (fp32) scaled by hat_d[row] at cvt time; B = wrn (fp16 perm16).
//   Writes g_gT[n][perm16-scattered m] = half_rn(D[m][n]).
// 128 CTAs of 128(M) x 256(N); 8 warps 2(M) x 4(N); warp tile 64 x 64.
// ---------------------------------------------------------------------------
__global__ void __launch_bounds__(256, 1)
gemm1_kernel(const float* __restrict__ feature,
             const float* __restrict__ hat_d)
{
    extern __shared__ char smraw[];
    const int tid = threadIdx.x;
    const int mtile = blockIdx.x;
    const int wid = tid >> 5;
    const int lane = tid & 31;
    const int wm = wid & 1;
    const int wn = wid >> 1;
    const int g = lane >> 2;
    const int t = lane & 3;

    float acc[4][8][4];
    #pragma unroll
    for (int mi = 0; mi < 4; ++mi)
        #pragma unroll
        for (int ni = 0; ni < 8; ++ni)
            #pragma unroll
            for (int r = 0; r < 4; ++r)
                acc[mi][ni][r] = 0.0f;

    const float* Agm = feature + (size_t)mtile * G1_TILE_M * INF;

    const int a_row = tid >> 1;
    const int a_kb  = tid & 1;
    const float hd = __ldg(hat_d + mtile * G1_TILE_M + a_row);
    const float* a_src_base = Agm + (size_t)a_row * INF + a_kb * 16;
    float a_stage[16];

    auto ldgA = [&](int s) {
        const float* p = a_src_base + s * KC;
        #pragma unroll
        for (int i = 0; i < 4; ++i) {
            float4 v = __ldg(reinterpret_cast<const float4*>(p + 4 * i));
            a_stage[4 * i + 0] = v.x;
            a_stage[4 * i + 1] = v.y;
            a_stage[4 * i + 2] = v.z;
            a_stage[4 * i + 3] = v.w;
        }
    };
    auto stsA = [&](int s) {
        __half* As = reinterpret_cast<__half*>(smraw + (s % NSTAGE) * G1_STAGE_BYTES);
        uint32_t w[8];
        #pragma unroll
        for (int q = 0; q < 4; ++q) {
            w[2 * q + 0] = f2h2(hd * a_stage[2 * q + 0], hd * a_stage[2 * q + 1]);
            w[2 * q + 1] = f2h2(hd * a_stage[2 * q + 8], hd * a_stage[2 * q + 9]);
        }
        uint32_t dst = smem_u32(As + a_row * PH + a_kb * 16);
        asm volatile("st.shared.v4.b32 [%0], {%1,%2,%3,%4};"
                     :: "r"(dst), "r"(w[0]), "r"(w[1]), "r"(w[2]), "r"(w[3]) : "memory");
        asm volatile("st.shared.v4.b32 [%0], {%1,%2,%3,%4};"
                     :: "r"(dst + 16), "r"(w[4]), "r"(w[5]), "r"(w[6]), "r"(w[7]) : "memory");
    };
    auto cpB = [&](int s) {
        __half* Bs = reinterpret_cast<__half*>(smraw + (s % NSTAGE) * G1_STAGE_BYTES) + G1_A_HALVES;
        const int k0 = s * KC;
        #pragma unroll
        for (int i = 0; i < 4; ++i) {
            int v = tid + i * 256;
            int row = v >> 2, j = v & 3;
            cp16(smem_u32(Bs + row * PH + j * 8),
                 g_wrn + (size_t)row * INF + k0 + j * 8);
        }
    };

    ldgA(0); stsA(0); ldgA(1);
    cpB(0);
    asm volatile("cp.async.commit_group;" ::: "memory");
    cpB(1);
    asm volatile("cp.async.commit_group;" ::: "memory");

    const int nstages = INF / KC;   // 16
    for (int s = 0; s < nstages; ++s) {
        asm volatile("cp.async.wait_group 1;" ::: "memory");
        __syncthreads();

        if (s + 1 < nstages) stsA(s + 1);
        if (s + 2 < nstages) { cpB(s + 2); ldgA(s + 2); }
        asm volatile("cp.async.commit_group;" ::: "memory");

        const __half* As = reinterpret_cast<const __half*>(smraw + (s % NSTAGE) * G1_STAGE_BYTES);
        const __half* Bs = As + G1_A_HALVES;
        const __half* Abase = As + (wm * 64 + g) * PH + 4 * t;
        const __half* Bbase = Bs + (wn * 64 + g) * PH + 4 * t;

        #pragma unroll
        for (int kk = 0; kk < 2; ++kk) {
            uint2 bv[8];
            #pragma unroll
            for (int ni = 0; ni < 8; ++ni)
                bv[ni] = *reinterpret_cast<const uint2*>(Bbase + ni * 8 * PH + kk * 16);
            #pragma unroll
            for (int mi = 0; mi < 4; ++mi) {
                const __half* p = Abase + mi * 16 * PH + kk * 16;
                uint2 lo = *reinterpret_cast<const uint2*>(p);
                uint2 hi = *reinterpret_cast<const uint2*>(p + 8 * PH);
                uint32_t a[4] = {lo.x, hi.x, lo.y, hi.y};
                #pragma unroll
                for (int ni = 0; ni < 8; ++ni)
                    mma_f16(acc[mi][ni], a, bv[ni].x, bv[ni].y);
            }
        }
    }

    // epilogue: write gT fp16 in perm16-scattered m layout
    const int mbase = mtile * G1_TILE_M + wm * 64;
    const int nbase = wn * 64;
    const int pg = 4 * (g >> 1) + (g & 1);

    #pragma unroll
    for (int mi = 0; mi < 4; ++mi) {
        int r0p = mbase + mi * 16 + pg;
        int r1p = r0p + 2;
        #pragma unroll
        for (int ni = 0; ni < 8; ++ni) {
            int c0 = nbase + ni * 8 + 2 * t;
            int c1 = c0 + 1;
            g_gT[(size_t)c0 * NROWS + r0p] = __float2half_rn(acc[mi][ni][0]);
            g_gT[(size_t)c1 * NROWS + r0p] = __float2half_rn(acc[mi][ni][1]);
            g_gT[(size_t)c0 * NROWS + r1p] = __float2half_rn(acc[mi][ni][2]);
            g_gT[(size_t)c1 * NROWS + r1p] = __float2half_rn(acc[mi][ni][3]);
        }
    }
}

// ---------------------------------------------------------------------------
// GEMM2: out = hat_d .* (A @ g + g) + b, fp16 MMA, 148 CTAs.
//   CTA b covers 7 x 16-row blocks starting at block min(7b, 1017) (tail CTAs
//   overlap; duplicate writes are byte-identical). N = full 256.
//   8 warps each own N-slice of 32; warp tile 112(M) x 32(N).
//   A fp32 in gmem -> LDG/cvt/STS (perm16); B = g_gT fp16 perm16 via cp.async.
// ---------------------------------------------------------------------------
__global__ void __launch_bounds__(256, 1)
gemm2_kernel(const float* __restrict__ Ap,
             const float* __restrict__ hat_d,
             const float* __restrict__ bias,
             float* __restrict__ out)
{
    extern __shared__ char smraw[];
    const int tid = threadIdx.x;
    const int bid = blockIdx.x;
    const int wid = tid >> 5;     // 0..7 = N slice
    const int lane = tid & 31;
    const int g = lane >> 2;
    const int t = lane & 3;

    int mblock = 7 * bid;
    if (mblock > MBLOCKS - G2_NMI) mblock = MBLOCKS - G2_NMI;
    const int mstart = mblock * 16;

    float acc[G2_NMI][4][4];
    #pragma unroll
    for (int mi = 0; mi < G2_NMI; ++mi)
        #pragma unroll
        for (int ni = 0; ni < 4; ++ni)
            #pragma unroll
            for (int r = 0; r < 4; ++r)
                acc[mi][ni][r] = 0.0f;

    const float* Agm = Ap + (size_t)mstart * NROWS;

    // A staging: threads 0..223 own (row = tid>>1, kblock = tid&1)
    const int a_row = tid >> 1;
    const int a_kb  = tid & 1;
    const bool a_act = (a_row < G2_TILE_M);
    const float* a_src_base = Agm + (size_t)a_row * NROWS + a_kb * 16;
    float a_stage[16];

    auto ldgA = [&](int s) {
        if (!a_act) return;
        const float* p = a_src_base + s * KC;
        #pragma unroll
        for (int i = 0; i < 4; ++i) {
            float4 v = __ldg(reinterpret_cast<const float4*>(p + 4 * i));
            a_stage[4 * i + 0] = v.x;
            a_stage[4 * i + 1] = v.y;
            a_stage[4 * i + 2] = v.z;
            a_stage[4 * i + 3] = v.w;
        }
    };
    auto stsA = [&](int s) {
        if (!a_act) return;
        __half* As = reinterpret_cast<__half*>(smraw + (s % NSTAGE) * G2_STAGE_BYTES);
        uint32_t w[8];
        #pragma unroll
        for (int q = 0; q < 4; ++q) {
            w[2 * q + 0] = f2h2(a_stage[2 * q + 0], a_stage[2 * q + 1]);
            w[2 * q + 1] = f2h2(a_stage[2 * q + 8], a_stage[2 * q + 9]);
        }
        uint32_t dst = smem_u32(As + a_row * PH + a_kb * 16);
        asm volatile("st.shared.v4.b32 [%0], {%1,%2,%3,%4};"
                     :: "r"(dst), "r"(w[0]), "r"(w[1]), "r"(w[2]), "r"(w[3]) : "memory");
        asm volatile("st.shared.v4.b32 [%0], {%1,%2,%3,%4};"
                     :: "r"(dst + 16), "r"(w[4]), "r"(w[5]), "r"(w[6]), "r"(w[7]) : "memory");
    };
    auto cpB = [&](int s) {
        __half* Bs = reinterpret_cast<__half*>(smraw + (s % NSTAGE) * G2_STAGE_BYTES) + G2_A_HALVES;
        const int k0 = s * KC;
        #pragma unroll
        for (int i = 0; i < 4; ++i) {
            int v = tid + i * 256;
            int row = v >> 2, j = v & 3;
            cp16(smem_u32(Bs + row * PH + j * 8),
                 g_gT + (size_t)row * NROWS + k0 + j * 8);
        }
    };

    ldgA(0); stsA(0); ldgA(1);
    cpB(0);
    asm volatile("cp.async.commit_group;" ::: "memory");
    cpB(1);
    asm volatile("cp.async.commit_group;" ::: "memory");

    const int nstages = NROWS / KC;    // 512
    for (int s = 0; s < nstages; ++s) {
        asm volatile("cp.async.wait_group 1;" ::: "memory");
        __syncthreads();

        if (s + 1 < nstages) stsA(s + 1);
        if (s + 2 < nstages) { cpB(s + 2); ldgA(s + 2); }
        asm volatile("cp.async.commit_group;" ::: "memory");

        const __half* As = reinterpret_cast<const __half*>(smraw + (s % NSTAGE) * G2_STAGE_BYTES);
        const __half* Bs = As + G2_A_HALVES;
        const __half* Abase = As + g * PH + 4 * t;
        const __half* Bbase = Bs + (wid * 32 + g) * PH + 4 * t;

        #pragma unroll
        for (int kk = 0; kk < 2; ++kk) {
            uint2 bv[4];
            #pragma unroll
            for (int ni = 0; ni < 4; ++ni)
                bv[ni] = *reinterpret_cast<const uint2*>(Bbase + ni * 8 * PH + kk * 16);
            #pragma unroll
            for (int mi = 0; mi < G2_NMI; ++mi) {
                const __half* p = Abase + mi * 16 * PH + kk * 16;
                uint2 lo = *reinterpret_cast<const uint2*>(p);
                uint2 hi = *reinterpret_cast<const uint2*>(p + 8 * PH);
                uint32_t a[4] = {lo.x, hi.x, lo.y, hi.y};
                #pragma unroll
                for (int ni = 0; ni < 4; ++ni)
                    mma_f16(acc[mi][ni], a, bv[ni].x, bv[ni].y);
            }
        }
    }

    // ---- epilogue: out[m][n] = hat_d[m]*(D + gT_perm[n][m]) + b[n] ----
    const int nbase = wid * 32;
    const int pg = 4 * (g >> 1) + (g & 1);

    #pragma unroll
    for (int mi = 0; mi < G2_NMI; ++mi) {
        int r0 = mstart + mi * 16 + g;
        int r1 = r0 + 8;
        int r0p = mstart + mi * 16 + pg;
        int r1p = r0p + 2;
        float h0 = __ldg(hat_d + r0);
        float h1 = __ldg(hat_d + r1);
        #pragma unroll
        for (int ni = 0; ni < 4; ++ni) {
            int c0 = nbase + ni * 8 + 2 * t;
            int c1 = c0 + 1;
            float b0v = __ldg(bias + c0);
            float b1v = __ldg(bias + c1);
            float g00 = __half2float(g_gT[(size_t)c0 * NROWS + r0p]);
            float g01 = __half2float(g_gT[(size_t)c1 * NROWS + r0p]);
            float g10 = __half2float(g_gT[(size_t)c0 * NROWS + r1p]);
            float g11 = __half2float(g_gT[(size_t)c1 * NROWS + r1p]);
            float2 v0, v1;
            v0.x = fmaf(h0, acc[mi][ni][0] + g00, b0v);
            v0.y = fmaf(h0, acc[mi][ni][1] + g01, b1v);
            v1.x = fmaf(h1, acc[mi][ni][2] + g10, b0v);
            v1.y = fmaf(h1, acc[mi][ni][3] + g11, b1v);
            *reinterpret_cast<float2*>(out + (size_t)r0 * OUTF + c0) = v0;
            *reinterpret_cast<float2*>(out + (size_t)r1 * OUTF + c0) = v1;
        }
    }
}

// ---------------------------------------------------------------------------
// Host side
// ---------------------------------------------------------------------------
extern "C" void kernel_launch(void* const* d_in, const int* in_sizes, int n_in,
                              void* d_out, int out_size) {
    const float *A = nullptr, *hat_d = nullptr, *feature = nullptr,
                *W = nullptr, *b = nullptr;
    for (int i = 0; i < n_in; ++i) {
        switch (in_sizes[i]) {
            case NROWS:       hat_d   = (const float*)d_in[i]; break;   // 16384
            case OUTF:        b       = (const float*)d_in[i]; break;   // 256
            case OUTF * INF:  W       = (const float*)d_in[i]; break;   // 131072
            case NROWS * INF: feature = (const float*)d_in[i]; break;   // 8388608
            default:          A       = (const float*)d_in[i]; break;   // 16384*16384
        }
    }

    static bool attr_set = false;
    if (!attr_set) {
        cudaFuncSetAttribute(gemm1_kernel,
                             cudaFuncAttributeMaxDynamicSharedMemorySize, G1_SMEM);
        cudaFuncSetAttribute(gemm2_kernel,
                             cudaFuncAttributeMaxDynamicSharedMemorySize, G2_SMEM);
        attr_set = true;
    }

    prep_w_kernel<<<64, 256>>>(W);

    // GEMM1: g^T = ((hat_d.*feature) @ W^T)^T, K = 512
    gemm1_kernel<<<NROWS / G1_TILE_M, 256, G1_SMEM>>>(feature, hat_d);

    // GEMM2: out = hat_d*(A@g + g) + b, K = 16384, 148 CTAs (16-row granular M)
    gemm2_kernel<<<NCTA2, 256, G2_SMEM>>>(A, hat_d, b, (float*)d_out);

    (void)out_size;
}

// round 15
// speedup vs baseline: 1.8464x; 1.0102x over previous
#include <cuda_runtime.h>
#include <cuda_fp16.h>
#include <cstdint>
#include <cstddef>

// ---------------------------------------------------------------------------
// Problem dims
// ---------------------------------------------------------------------------
#define NROWS 16384
#define INF   512
#define OUTF  256

#define PH    48             // smem pitch in halves (96 B) for all fp16 tiles
#define KC    32             // K elems per pipeline stage (2 k16 blocks)
#define NSTAGE 3

// ---- Unified GEMM tiling: 112(M) x 256(N) per CTA, 148 CTAs ----
#define TILE_M 112                                   // 7 x 16-row blocks
#define NMI    7
#define A_HALVES (TILE_M * PH)                       // 5376
#define B_HALVES (OUTF * PH)                         // 12288
#define STAGE_BYTES ((A_HALVES + B_HALVES) * 2)      // 35328
#define SMEM_BYTES (NSTAGE * STAGE_BYTES)            // 105984
#define NCTA 148
#define MBLOCKS (NROWS / 16)                         // 1024

// within-16-block k permutation for fp16 operands:
//   logical k -> phys = 4*((k>>1)&3) + 2*((k>>3)&1) + (k&1)
// => thread t's m16n8k16 halves {2t,2t+1,2t+8,2t+9} land at phys [4t..4t+3] (one LDS.64)
__host__ __device__ __forceinline__ int perm16(int k) {
    return 4 * ((k >> 1) & 3) + 2 * ((k >> 3) & 1) + (k & 1);
}

// ---------------------------------------------------------------------------
// Scratch (__device__ globals: allocation-free)
// ---------------------------------------------------------------------------
__device__ __align__(256) __half g_wrn[(size_t)OUTF * INF];    // W, fp16 rn, perm16 k-layout
__device__ __align__(256) __half g_gT [(size_t)OUTF * NROWS];  // g^T, fp16 rn, perm16 k-layout

// ---------------------------------------------------------------------------
// Helpers
// ---------------------------------------------------------------------------
__device__ __forceinline__ uint32_t smem_u32(const void* p) {
    uint32_t a;
    asm("{ .reg .u64 t; cvta.to.shared.u64 t, %1; cvt.u32.u64 %0, t; }" : "=r"(a) : "l"(p));
    return a;
}

__device__ __forceinline__ void cp16(uint32_t dst_smem, const void* src) {
    asm volatile("cp.async.cg.shared.global [%0], [%1], 16;"
                 :: "r"(dst_smem), "l"(src) : "memory");
}

__device__ __forceinline__ uint32_t f2h2(float lo, float hi) {
    uint32_t r;
    asm("cvt.rn.f16x2.f32 %0, %2, %1;" : "=r"(r) : "f"(lo), "f"(hi));
    return r;
}

__device__ __forceinline__ void mma_f16(float* d, const uint32_t* a, uint32_t b0, uint32_t b1) {
    asm volatile(
        "mma.sync.aligned.m16n8k16.row.col.f32.f16.f16.f32 "
        "{%0,%1,%2,%3}, {%4,%5,%6,%7}, {%8,%9}, {%0,%1,%2,%3};"
        : "+f"(d[0]), "+f"(d[1]), "+f"(d[2]), "+f"(d[3])
        : "r"(a[0]), "r"(a[1]), "r"(a[2]), "r"(a[3]),
          "r"(b0), "r"(b1));
}

// ---------------------------------------------------------------------------
// Prep: wrn[r][perm16(k)] = half_rn(W[r][k])
// ---------------------------------------------------------------------------
__global__ void prep_w_kernel(const float* __restrict__ W) {
    size_t i = (size_t)blockIdx.x * blockDim.x + threadIdx.x;
    size_t stride = (size_t)gridDim.x * blockDim.x;
    size_t wtotal = (size_t)OUTF * INF;
    for (size_t idx = i; idx < wtotal; idx += stride) {
        int k = (int)(idx & (INF - 1));
        size_t row = idx >> 9;
        int kp = (k & ~15) | perm16(k & 15);
        g_wrn[row * INF + kp] = __float2half_rn(W[idx]);
    }
}

// ---------------------------------------------------------------------------
// Unified fp16 mma.sync GEMM, 148 CTAs, CTA = 112(M) x 256(N).
//   CTA b covers 7 x 16-row blocks starting at block min(7b, 1017) (tail CTAs
//   overlap; duplicate writes are byte-identical). 8 warps own N-slices of 32.
//   A fp32 in gmem -> LDG/cvt/STS (perm16 smem), optional hat_d row scaling.
//   B fp16 perm16 in gmem via cp.async.
//   mode 0 (GEMM1): A=feature (scaled by hat_d), B=wrn, K=512;
//                   writes g_gT[n][perm16-scattered m] = half_rn(D[m][n]).
//   mode 1 (GEMM2): A=adjacency, B=gT, K=16384;
//                   out[m][n] = hat_d[m]*(D[m][n] + gT_perm[n][m]) + b[n].
// ---------------------------------------------------------------------------
__global__ void __launch_bounds__(256, 1)
gemm_f16_kernel(const float* __restrict__ Ap, int a_ld,
                const __half* __restrict__ Bp, int b_ld,
                int nstages, int mode,
                const float* __restrict__ hat_d,
                const float* __restrict__ bias,
                float* __restrict__ out)
{
    extern __shared__ char smraw[];
    const int tid = threadIdx.x;
    const int bid = blockIdx.x;
    const int wid = tid >> 5;     // 0..7 = N slice
    const int lane = tid & 31;
    const int g = lane >> 2;
    const int t = lane & 3;

    int mblock = 7 * bid;
    if (mblock > MBLOCKS - NMI) mblock = MBLOCKS - NMI;
    const int mstart = mblock * 16;

    float acc[NMI][4][4];
    #pragma unroll
    for (int mi = 0; mi < NMI; ++mi)
        #pragma unroll
        for (int ni = 0; ni < 4; ++ni)
            #pragma unroll
            for (int r = 0; r < 4; ++r)
                acc[mi][ni][r] = 0.0f;

    const float* Agm = Ap + (size_t)mstart * a_ld;

    // A staging: threads 0..223 own (row = tid>>1, kblock = tid&1)
    const int a_row = tid >> 1;
    const int a_kb  = tid & 1;
    const bool a_act = (a_row < TILE_M);
    const float* a_src_base = Agm + (size_t)a_row * a_ld + a_kb * 16;
    const float hd_s = (mode == 0 && a_act) ? __ldg(hat_d + mstart + a_row) : 1.0f;
    float a_stage[16];

    auto ldgA = [&](int s) {
        if (!a_act) return;
        const float* p = a_src_base + s * KC;
        #pragma unroll
        for (int i = 0; i < 4; ++i) {
            float4 v = __ldg(reinterpret_cast<const float4*>(p + 4 * i));
            a_stage[4 * i + 0] = v.x;
            a_stage[4 * i + 1] = v.y;
            a_stage[4 * i + 2] = v.z;
            a_stage[4 * i + 3] = v.w;
        }
    };
    auto stsA = [&](int s) {
        if (!a_act) return;
        __half* As = reinterpret_cast<__half*>(smraw + (s % NSTAGE) * STAGE_BYTES);
        uint32_t w[8];
        #pragma unroll
        for (int q = 0; q < 4; ++q) {
            w[2 * q + 0] = f2h2(hd_s * a_stage[2 * q + 0], hd_s * a_stage[2 * q + 1]);
            w[2 * q + 1] = f2h2(hd_s * a_stage[2 * q + 8], hd_s * a_stage[2 * q + 9]);
        }
        uint32_t dst = smem_u32(As + a_row * PH + a_kb * 16);
        asm volatile("st.shared.v4.b32 [%0], {%1,%2,%3,%4};"
                     :: "r"(dst), "r"(w[0]), "r"(w[1]), "r"(w[2]), "r"(w[3]) : "memory");
        asm volatile("st.shared.v4.b32 [%0], {%1,%2,%3,%4};"
                     :: "r"(dst + 16), "r"(w[4]), "r"(w[5]), "r"(w[6]), "r"(w[7]) : "memory");
    };
    auto cpB = [&](int s) {
        __half* Bs = reinterpret_cast<__half*>(smraw + (s % NSTAGE) * STAGE_BYTES) + A_HALVES;
        const int k0 = s * KC;
        #pragma unroll
        for (int i = 0; i < 4; ++i) {
            int v = tid + i * 256;
            int row = v >> 2, j = v & 3;
            cp16(smem_u32(Bs + row * PH + j * 8),
                 Bp + (size_t)row * b_ld + k0 + j * 8);
        }
    };

    ldgA(0); stsA(0); ldgA(1);
    cpB(0);
    asm volatile("cp.async.commit_group;" ::: "memory");
    cpB(1);
    asm volatile("cp.async.commit_group;" ::: "memory");

    for (int s = 0; s < nstages; ++s) {
        asm volatile("cp.async.wait_group 1;" ::: "memory");
        __syncthreads();

        if (s + 1 < nstages) stsA(s + 1);
        if (s + 2 < nstages) { cpB(s + 2); ldgA(s + 2); }
        asm volatile("cp.async.commit_group;" ::: "memory");

        const __half* As = reinterpret_cast<const __half*>(smraw + (s % NSTAGE) * STAGE_BYTES);
        const __half* Bs = As + A_HALVES;
        const __half* Abase = As + g * PH + 4 * t;
        const __half* Bbase = Bs + (wid * 32 + g) * PH + 4 * t;

        #pragma unroll
        for (int kk = 0; kk < 2; ++kk) {
            uint2 bv[4];
            #pragma unroll
            for (int ni = 0; ni < 4; ++ni)
                bv[ni] = *reinterpret_cast<const uint2*>(Bbase + ni * 8 * PH + kk * 16);
            #pragma unroll
            for (int mi = 0; mi < NMI; ++mi) {
                const __half* p = Abase + mi * 16 * PH + kk * 16;
                uint2 lo = *reinterpret_cast<const uint2*>(p);
                uint2 hi = *reinterpret_cast<const uint2*>(p + 8 * PH);
                uint32_t a[4] = {lo.x, hi.x, lo.y, hi.y};
                #pragma unroll
                for (int ni = 0; ni < 4; ++ni)
                    mma_f16(acc[mi][ni], a, bv[ni].x, bv[ni].y);
            }
        }
    }

    // ---- epilogue ----
    const int nbase = wid * 32;
    const int pg = 4 * (g >> 1) + (g & 1);

    if (mode == 0) {
        #pragma unroll
        for (int mi = 0; mi < NMI; ++mi) {
            int r0p = mstart + mi * 16 + pg;
            int r1p = r0p + 2;
            #pragma unroll
            for (int ni = 0; ni < 4; ++ni) {
                int c0 = nbase + ni * 8 + 2 * t;
                int c1 = c0 + 1;
                g_gT[(size_t)c0 * NROWS + r0p] = __float2half_rn(acc[mi][ni][0]);
                g_gT[(size_t)c1 * NROWS + r0p] = __float2half_rn(acc[mi][ni][1]);
                g_gT[(size_t)c0 * NROWS + r1p] = __float2half_rn(acc[mi][ni][2]);
                g_gT[(size_t)c1 * NROWS + r1p] = __float2half_rn(acc[mi][ni][3]);
            }
        }
    } else {
        #pragma unroll
        for (int mi = 0; mi < NMI; ++mi) {
            int r0 = mstart + mi * 16 + g;
            int r1 = r0 + 8;
            int r0p = mstart + mi * 16 + pg;
            int r1p = r0p + 2;
            float h0 = __ldg(hat_d + r0);
            float h1 = __ldg(hat_d + r1);
            #pragma unroll
            for (int ni = 0; ni < 4; ++ni) {
                int c0 = nbase + ni * 8 + 2 * t;
                int c1 = c0 + 1;
                float b0v = __ldg(bias + c0);
                float b1v = __ldg(bias + c1);
                float g00 = __half2float(g_gT[(size_t)c0 * NROWS + r0p]);
                float g01 = __half2float(g_gT[(size_t)c1 * NROWS + r0p]);
                float g10 = __half2float(g_gT[(size_t)c0 * NROWS + r1p]);
                float g11 = __half2float(g_gT[(size_t)c1 * NROWS + r1p]);
                float2 v0, v1;
                v0.x = fmaf(h0, acc[mi][ni][0] + g00, b0v);
                v0.y = fmaf(h0, acc[mi][ni][1] + g01, b1v);
                v1.x = fmaf(h1, acc[mi][ni][2] + g10, b0v);
                v1.y = fmaf(h1, acc[mi][ni][3] + g11, b1v);
                *reinterpret_cast<float2*>(out + (size_t)r0 * OUTF + c0) = v0;
                *reinterpret_cast<float2*>(out + (size_t)r1 * OUTF + c0) = v1;
            }
        }
    }
}

// ---------------------------------------------------------------------------
// Host side
// ---------------------------------------------------------------------------
extern "C" void kernel_launch(void* const* d_in, const int* in_sizes, int n_in,
                              void* d_out, int out_size) {
    const float *A = nullptr, *hat_d = nullptr, *feature = nullptr,
                *W = nullptr, *b = nullptr;
    for (int i = 0; i < n_in; ++i) {
        switch (in_sizes[i]) {
            case NROWS:       hat_d   = (const float*)d_in[i]; break;   // 16384
            case OUTF:        b       = (const float*)d_in[i]; break;   // 256
            case OUTF * INF:  W       = (const float*)d_in[i]; break;   // 131072
            case NROWS * INF: feature = (const float*)d_in[i]; break;   // 8388608
            default:          A       = (const float*)d_in[i]; break;   // 16384*16384
        }
    }

    void *p_wrn = nullptr, *p_gT = nullptr;
    cudaGetSymbolAddress(&p_wrn, g_wrn);
    cudaGetSymbolAddress(&p_gT,  g_gT);

    static bool attr_set = false;
    if (!attr_set) {
        cudaFuncSetAttribute(gemm_f16_kernel,
                             cudaFuncAttributeMaxDynamicSharedMemorySize, SMEM_BYTES);
        attr_set = true;
    }

    prep_w_kernel<<<256, 256>>>(W);

    // GEMM1: g^T = ((hat_d.*feature) @ W^T)^T, K = 512 -> 16 stages
    gemm_f16_kernel<<<NCTA, 256, SMEM_BYTES>>>(
        feature, INF, (const __half*)p_wrn, INF,
        INF / KC, 0, hat_d, nullptr, nullptr);

    // GEMM2: out = hat_d*(A@g + g) + b, K = 16384 -> 512 stages
    gemm_f16_kernel<<<NCTA, 256, SMEM_BYTES>>>(
        A, NROWS, (const __half*)p_gT, NROWS,
        NROWS / KC, 1, hat_d, b, (float*)d_out);

    (void)out_size;
}